// round 5
// baseline (speedup 1.0000x reference)
#include <cuda_runtime.h>
#include <cuda_bf16.h>
#include <cstdint>

#define NTOK 8192
#define EDIM 64
#define SCALE 0.35355339059327373f   // 1/sqrt(8)

// Q/K: s8 planes interleaved per row: 128B = [hi 64B | lo 64B], SW128-swizzled 16B chunks.
// V: bf16 hi/lo planes, 128B rows, SW128-swizzled (validated layout).
__device__ uint32_t g_q8[NTOK*32];
__device__ uint32_t g_k8[NTOK*32];
__device__ uint32_t g_vh[NTOK*32], g_vl[NTOK*32];
__device__ float    g_ov[NTOK*EDIM];

// exp2 constants: s = S_hh*2^-13 + S_mid*2^-20 ; arg = s*log2(e)
#define CA_F ((float)(1.4426950408889634 / 8192.0))
#define CB_F ((float)(1.4426950408889634 / 1048576.0))
#define C0_F ((float)(-12582912.0 * (1.4426950408889634/8192.0 + 1.4426950408889634/1048576.0)))

// ======================= helpers =======================
__device__ __forceinline__ uint32_t smem_u32(const void* p) {
    uint32_t a;
    asm("{ .reg .u64 t; cvta.to.shared.u64 t, %1; cvt.u32.u64 %0, t; }" : "=r"(a) : "l"(p));
    return a;
}
__device__ __forceinline__ void cp16(uint32_t dst, const void* src) {
    asm volatile("{ .reg .u64 g; cvta.to.global.u64 g, %1; cp.async.cg.shared.global [%0], [g], 16; }"
                 :: "r"(dst), "l"(src) : "memory");
}
#define CP_COMMIT() asm volatile("cp.async.commit_group;" ::: "memory")
#define CP_WAIT(n)  asm volatile("cp.async.wait_group %0;" :: "n"(n) : "memory")

#define LDSM4(r, a) \
    asm volatile("ldmatrix.sync.aligned.m8n8.x4.shared.b16 {%0,%1,%2,%3}, [%4];" \
        : "=r"((r)[0]), "=r"((r)[1]), "=r"((r)[2]), "=r"((r)[3]) : "r"(a))
#define LDSM4T(r, a) \
    asm volatile("ldmatrix.sync.aligned.m8n8.x4.trans.shared.b16 {%0,%1,%2,%3}, [%4];" \
        : "=r"((r)[0]), "=r"((r)[1]), "=r"((r)[2]), "=r"((r)[3]) : "r"(a))

#define MMA(c, a, b0, b1) \
    asm volatile("mma.sync.aligned.m16n8k16.row.col.f32.bf16.bf16.f32 " \
        "{%0,%1,%2,%3}, {%4,%5,%6,%7}, {%8,%9}, {%0,%1,%2,%3};" \
        : "+f"((c)[0]), "+f"((c)[1]), "+f"((c)[2]), "+f"((c)[3]) \
        : "r"((a)[0]), "r"((a)[1]), "r"((a)[2]), "r"((a)[3]), "r"(b0), "r"(b1))

#define MMAS8(c, a0, a1, a2, a3, b0, b1) \
    asm volatile("mma.sync.aligned.m16n8k32.row.col.s32.s8.s8.s32 " \
        "{%0,%1,%2,%3}, {%4,%5,%6,%7}, {%8,%9}, {%0,%1,%2,%3};" \
        : "+r"((c)[0]), "+r"((c)[1]), "+r"((c)[2]), "+r"((c)[3]) \
        : "r"(a0), "r"(a1), "r"(a2), "r"(a3), "r"(b0), "r"(b1))

__device__ __forceinline__ float ex2f(float x) {
    float p; asm("ex2.approx.f32 %0, %1;" : "=f"(p) : "f"(x)); return p;
}
// swizzled smem address: 128B rows, 16B chunk index XOR (row&7)
__device__ __forceinline__ uint32_t swadr(uint32_t base, int row, int bytecol) {
    return base + row*128 + ((((bytecol >> 4) ^ (row & 7)) << 4));
}
__device__ __forceinline__ void packhl(float a, float b, uint32_t& h, uint32_t& l) {
    __nv_bfloat16 ah = __float2bfloat16(a), bh = __float2bfloat16(b);
    float ra = a - __bfloat162float(ah), rb = b - __bfloat162float(bh);
    __nv_bfloat16 al = __float2bfloat16(ra), bl = __float2bfloat16(rb);
    h = (uint32_t)__bfloat16_as_ushort(ah) | ((uint32_t)__bfloat16_as_ushort(bh) << 16);
    l = (uint32_t)__bfloat16_as_ushort(al) | ((uint32_t)__bfloat16_as_ushort(bl) << 16);
}

// smem: Q8 0..8K ; buf b at 8192 + b*24576 : [K8 8K | Vh 8K | Vl 8K]
#define SBUF(b)    (8192 + (b)*24576)
#define SMEM_FLASH 57344

// ---------------- Kernel 1: QKV projection + quantum map + packing ----------------
// 256 thr, 128 rows/block; thread: rows rg,rg+32,rg+64,rg+96 x cols c0..c0+7.
__global__ void __launch_bounds__(256) qkv_kernel(
    const float* __restrict__ x,
    const float* __restrict__ wq, const float* __restrict__ bq,
    const float* __restrict__ wk, const float* __restrict__ bk,
    const float* __restrict__ wv, const float* __restrict__ bv,
    const float* __restrict__ theta)
{
    extern __shared__ float sm1[];
    float* wt = sm1;            // [64][65]
    float* xs = sm1 + 4160;     // [128][65]
    float* bs = sm1 + 12480;    // [64]
    float* cs = bs + 64;        // [64]

    const int tid  = threadIdx.x;
    const int m    = blockIdx.y;
    const int row0 = blockIdx.x * 128;

    const float* w  = (m == 0) ? wq : ((m == 1) ? wk : wv);
    const float* bb = (m == 0) ? bq : ((m == 1) ? bk : bv);
    for (int i = tid; i < 4096; i += 256)
        wt[(i >> 6)*65 + (i & 63)] = w[i];
    if (tid < 64) {
        bs[tid] = bb[tid];
        cs[tid] = ((m == 0) ? SCALE : 1.0f) * __cosf(theta[tid]);
    }
    for (int i = tid; i < 8192; i += 256)
        xs[(i >> 6)*65 + (i & 63)] = x[(size_t)row0*64 + i];
    __syncthreads();

    const int rg = tid & 31;
    const int c0 = (tid >> 5) * 8;

    float acc[4][8];
    #pragma unroll
    for (int i = 0; i < 4; i++)
        #pragma unroll
        for (int j = 0; j < 8; j++) acc[i][j] = bs[c0 + j];

    #pragma unroll 8
    for (int d = 0; d < 64; d++) {
        float wv8[8];
        #pragma unroll
        for (int j = 0; j < 8; j++) wv8[j] = wt[(c0 + j)*65 + d];
        #pragma unroll
        for (int i = 0; i < 4; i++) {
            float xv = xs[(rg + 32*i)*65 + d];
            #pragma unroll
            for (int j = 0; j < 8; j++)
                acc[i][j] = fmaf(xv, wv8[j], acc[i][j]);
        }
    }

    const float qscale = (m == 0) ? 16384.0f : 8192.0f;
    #pragma unroll
    for (int i = 0; i < 4; i++) {
        const int gr = row0 + rg + 32*i;
        float v[8];
        #pragma unroll
        for (int j = 0; j < 8; j++)
            v[j] = cs[c0 + j] * __cosf(acc[i][j]);

        if (m < 2) {
            uint32_t hwrd[2] = {0, 0}, lwrd[2] = {0, 0};
            #pragma unroll
            for (int j = 0; j < 8; j++) {
                int qi = __float2int_rn(v[j] * qscale);
                int hi = (qi + 64) >> 7;
                int lo = qi - (hi << 7);
                hwrd[j >> 2] |= ((uint32_t)(uint8_t)(int8_t)hi) << ((j & 3)*8);
                lwrd[j >> 2] |= ((uint32_t)(uint8_t)(int8_t)lo) << ((j & 3)*8);
            }
            uint32_t* dst = (m == 0) ? g_q8 : g_k8;
            int chH = c0 >> 4;
            int wH = (((chH     ^ (gr & 7)) << 2)) + ((c0 & 15) >> 2);
            int wL = ((((chH+4) ^ (gr & 7)) << 2)) + ((c0 & 15) >> 2);
            dst[gr*32 + wH]     = hwrd[0];
            dst[gr*32 + wH + 1] = hwrd[1];
            dst[gr*32 + wL]     = lwrd[0];
            dst[gr*32 + wL + 1] = lwrd[1];
        } else {
            int cp0 = c0 >> 1;
            int wd0 = (((cp0 >> 2) ^ (gr & 7)) << 2);
            #pragma unroll
            for (int p = 0; p < 4; p++) {
                uint32_t hw, lw;
                packhl(v[2*p], v[2*p + 1], hw, lw);
                g_vh[gr*32 + wd0 + p] = hw;
                g_vl[gr*32 + wd0 + p] = lw;
            }
        }
    }
}

// ---------------- tile copy: 64 keys x (K8, Vh, Vl), pre-swizzled ----------------
__device__ __forceinline__ void copy_tile(uint32_t sb, int tid, int buf, int kb) {
    #pragma unroll
    for (int j = 0; j < 12; j++) {
        int c = j*128 + tid;
        int arr = c >> 9;          // 0:k8 1:vh 2:vl (constant per j)
        int rem = c & 511;
        int row = rem >> 3, ch = rem & 7;
        const uint32_t* sp = (arr == 0) ? g_k8 : (arr == 1) ? g_vh : g_vl;
        cp16(sb + SBUF(buf) + arr*8192 + row*128 + ch*16,
             sp + (size_t)(kb*64 + row)*32 + ch*4);
    }
}

// ---------------- Kernel 2: s8-S / bf16-PV flash attention (no-max softmax) -------
__global__ void __launch_bounds__(128, 1) flash_kernel()
{
    extern __shared__ char smem[];
    uint32_t sb = smem_u32(smem);
    const int tid  = threadIdx.x;
    const int wid  = tid >> 5;
    const int lane = tid & 31;
    const int qb   = blockIdx.x;           // 64 q-rows per CTA

    // ---- prologue copies: Q8, tile0, tile1 ----
    #pragma unroll
    for (int j = 0; j < 4; j++) {
        int c = j*128 + tid;
        int row = c >> 3, ch = c & 7;
        cp16(sb + row*128 + ch*16, g_q8 + (size_t)(qb*64 + row)*32 + ch*4);
    }
    CP_COMMIT();
    copy_tile(sb, tid, 0, 0); CP_COMMIT();
    copy_tile(sb, tid, 1, 1); CP_COMMIT();
    CP_WAIT(2);
    __syncthreads();

    // ---- Q A-fragments: s8 hi/lo, 2 k-steps each ----
    uint32_t qh[2][4], ql[2][4];
    {
        const int row = wid*16 + (lane & 15);
        const int cb  = (lane >> 4) * 16;
        #pragma unroll
        for (int ks = 0; ks < 2; ks++) {
            LDSM4(qh[ks], swadr(sb, row, ks*32 + cb));
            LDSM4(ql[ks], swadr(sb, row, 64 + ks*32 + cb));
        }
    }

    float o[8][4];
    #pragma unroll
    for (int db = 0; db < 8; db++)
        #pragma unroll
        for (int i = 0; i < 4; i++) o[db][i] = 0.f;
    float lg = 0.f, lg8 = 0.f;

    const int li = lane & 7, ls = lane >> 3;
    const int lr = (lane >> 3) & 1, lc = lane >> 4;

    #pragma unroll 1
    for (int kb = 0; kb < 128; kb++) {
        const int b = kb & 1;
        if (kb < 126) { CP_WAIT(1); } else { CP_WAIT(0); }
        __syncthreads();

        const uint32_t kb8 = sb + SBUF(b);
        const uint32_t vbh = kb8 + 8192;
        const uint32_t vbl = kb8 + 16384;

        #pragma unroll
        for (int g = 0; g < 2; g++) {
            // ---- S (s8): S_hh exact, S_mid = qh*kl + ql*kh ----
            int shh[4][4], smid[4][4];
            #pragma unroll
            for (int ln = 0; ln < 4; ln++)
                #pragma unroll
                for (int t = 0; t < 4; t++) { shh[ln][t] = 0; smid[ln][t] = 0; }

            #pragma unroll
            for (int ln = 0; ln < 4; ln++) {
                const int nb = g*4 + ln;
                uint32_t kh4[4], kl4[4];
                LDSM4(kh4, swadr(kb8, nb*8 + li, ls*16));
                LDSM4(kl4, swadr(kb8, nb*8 + li, 64 + ls*16));
                MMAS8(shh[ln],  qh[0][0], qh[0][1], qh[0][2], qh[0][3], kh4[0], kh4[1]);
                MMAS8(shh[ln],  qh[1][0], qh[1][1], qh[1][2], qh[1][3], kh4[2], kh4[3]);
                MMAS8(smid[ln], qh[0][0], qh[0][1], qh[0][2], qh[0][3], kl4[0], kl4[1]);
                MMAS8(smid[ln], qh[1][0], qh[1][1], qh[1][2], qh[1][3], kl4[2], kl4[3]);
                MMAS8(smid[ln], ql[0][0], ql[0][1], ql[0][2], ql[0][3], kh4[0], kh4[1]);
                MMAS8(smid[ln], ql[1][0], ql[1][1], ql[1][2], ql[1][3], kh4[2], kh4[3]);
            }

            // ---- exp (fused int->float->ex2) + pack P A-frags ----
            uint32_t ph[2][4], pl[2][4];
            #pragma unroll
            for (int ln = 0; ln < 4; ln++) {
                float e[4];
                #pragma unroll
                for (int t = 0; t < 4; t++) {
                    float f1 = __int_as_float(0x4B400000 + shh[ln][t]);
                    float f2 = __int_as_float(0x4B400000 + smid[ln][t]);
                    e[t] = ex2f(fmaf(f1, CA_F, fmaf(f2, CB_F, C0_F)));
                }
                lg  += e[0] + e[1];
                lg8 += e[2] + e[3];
                const int kcl = ln >> 1, rb = (ln & 1) * 2;
                packhl(e[0], e[1], ph[kcl][rb + 0], pl[kcl][rb + 0]);
                packhl(e[2], e[3], ph[kcl][rb + 1], pl[kcl][rb + 1]);
            }

            // ---- O += P V (bf16 3-term) over this group's 32 keys ----
            #pragma unroll
            for (int kcl = 0; kcl < 2; kcl++) {
                const int kcg = g*2 + kcl;
                uint32_t vf[4][4];
                #pragma unroll
                for (int dp = 0; dp < 4; dp++)
                    LDSM4T(vf[dp], swadr(vbh, kcg*16 + lr*8 + li, 32*dp + lc*16));
                #pragma unroll
                for (int db = 0; db < 8; db++)
                    MMA(o[db], ph[kcl], vf[db>>1][(db&1)*2], vf[db>>1][(db&1)*2+1]);
                #pragma unroll
                for (int db = 0; db < 8; db++)
                    MMA(o[db], pl[kcl], vf[db>>1][(db&1)*2], vf[db>>1][(db&1)*2+1]);
                #pragma unroll
                for (int dp = 0; dp < 4; dp++)
                    LDSM4T(vf[dp], swadr(vbl, kcg*16 + lr*8 + li, 32*dp + lc*16));
                #pragma unroll
                for (int db = 0; db < 8; db++)
                    MMA(o[db], ph[kcl], vf[db>>1][(db&1)*2], vf[db>>1][(db&1)*2+1]);
            }
        }

        __syncthreads();
        if (kb + 2 < 128) { copy_tile(sb, tid, b, kb + 2); CP_COMMIT(); }
    }

    // ---- epilogue: quad-reduce row sums, normalize, store ----
    lg  += __shfl_xor_sync(0xffffffffu, lg, 1);
    lg  += __shfl_xor_sync(0xffffffffu, lg, 2);
    lg8 += __shfl_xor_sync(0xffffffffu, lg8, 1);
    lg8 += __shfl_xor_sync(0xffffffffu, lg8, 2);
    const float ig = 1.f/lg, ig8 = 1.f/lg8;
    const int gq = lane >> 2, t = lane & 3;
    const int n = qb*64 + wid*16 + gq;
    #pragma unroll
    for (int db = 0; db < 8; db++) {
        int d = db*8 + 2*t;
        *reinterpret_cast<float2*>(&g_ov[(size_t)n*64 + d])       = make_float2(o[db][0]*ig,  o[db][1]*ig);
        *reinterpret_cast<float2*>(&g_ov[(size_t)(n + 8)*64 + d]) = make_float2(o[db][2]*ig8, o[db][3]*ig8);
    }
}

// ---------------- Kernel 3: output projection ----------------
__global__ void __launch_bounds__(256) proj_kernel(
    const float* __restrict__ wo, const float* __restrict__ bo,
    float* __restrict__ out)
{
    __shared__ float wt[64*65];
    __shared__ float bs[64];
    __shared__ float os[32*64];
    const int tid = threadIdx.x;
    const int row0 = blockIdx.x * 32;
    for (int i = tid; i < 4096; i += 256)
        wt[(i >> 6)*65 + (i & 63)] = wo[i];
    if (tid < 64) bs[tid] = bo[tid];
    for (int i = tid; i < 2048; i += 256)
        os[i] = g_ov[(size_t)row0*64 + i];
    __syncthreads();

    for (int tI = tid; tI < 2048; tI += 256) {
        int row = tI >> 6, col = tI & 63;
        float acc = bs[col];
        const float* wrow = &wt[col*65];
        const float* orow = &os[row*64];
        #pragma unroll
        for (int d = 0; d < 64; d++)
            acc = fmaf(orow[d], wrow[d], acc);
        out[(row0 + row)*64 + col] = acc;
    }
}

// ---------------- launch ----------------
extern "C" void kernel_launch(void* const* d_in, const int* in_sizes, int n_in,
                              void* d_out, int out_size)
{
    const float* x  = (const float*)d_in[0];
    const float* wq = (const float*)d_in[1];
    const float* bq = (const float*)d_in[2];
    const float* wk = (const float*)d_in[3];
    const float* bk = (const float*)d_in[4];
    const float* wv = (const float*)d_in[5];
    const float* bv = (const float*)d_in[6];
    const float* th = (const float*)d_in[7];
    const float* wo = (const float*)d_in[8];
    const float* bo = (const float*)d_in[9];
    float* out = (float*)d_out;

    const int QKV_SMEM = 12608 * 4;   // 50432 B
    cudaFuncSetAttribute(qkv_kernel,  cudaFuncAttributeMaxDynamicSharedMemorySize, QKV_SMEM);
    cudaFuncSetAttribute(flash_kernel, cudaFuncAttributeMaxDynamicSharedMemorySize, SMEM_FLASH);

    qkv_kernel<<<dim3(NTOK/128, 3), 256, QKV_SMEM>>>(x, wq, bq, wk, bk, wv, bv, th);
    flash_kernel<<<128, 128, SMEM_FLASH>>>();
    proj_kernel<<<NTOK/32, 256>>>(wo, bo, out);
}

// round 6
// speedup vs baseline: 3.5040x; 3.5040x over previous
#include <cuda_runtime.h>
#include <cuda_bf16.h>
#include <cstdint>

#define NTOK 8192
#define EDIM 64
#define SCALE 0.35355339059327373f   // 1/sqrt(8)

// packed bf16x2 words: [row][32 words], SW128-swizzled 16B chunks within 128B rows.
__device__ uint32_t g_qh[NTOK*32], g_ql[NTOK*32];
__device__ uint32_t g_kh[NTOK*32];
__device__ uint32_t g_vh[NTOK*32];
__device__ float    g_ov[NTOK*EDIM];

// ======================= helpers =======================
__device__ __forceinline__ uint32_t smem_u32(const void* p) {
    uint32_t a;
    asm("{ .reg .u64 t; cvta.to.shared.u64 t, %1; cvt.u32.u64 %0, t; }" : "=r"(a) : "l"(p));
    return a;
}
__device__ __forceinline__ void cp16(uint32_t dst, const void* src) {
    asm volatile("{ .reg .u64 g; cvta.to.global.u64 g, %1; cp.async.cg.shared.global [%0], [g], 16; }"
                 :: "r"(dst), "l"(src) : "memory");
}
#define CP_COMMIT() asm volatile("cp.async.commit_group;" ::: "memory")
#define CP_WAIT(n)  asm volatile("cp.async.wait_group %0;" :: "n"(n) : "memory")

#define LDSM4(r, a) \
    asm volatile("ldmatrix.sync.aligned.m8n8.x4.shared.b16 {%0,%1,%2,%3}, [%4];" \
        : "=r"((r)[0]), "=r"((r)[1]), "=r"((r)[2]), "=r"((r)[3]) : "r"(a))
#define LDSM4T(r, a) \
    asm volatile("ldmatrix.sync.aligned.m8n8.x4.trans.shared.b16 {%0,%1,%2,%3}, [%4];" \
        : "=r"((r)[0]), "=r"((r)[1]), "=r"((r)[2]), "=r"((r)[3]) : "r"(a))

#define MMA(c, a, b0, b1) \
    asm volatile("mma.sync.aligned.m16n8k16.row.col.f32.bf16.bf16.f32 " \
        "{%0,%1,%2,%3}, {%4,%5,%6,%7}, {%8,%9}, {%0,%1,%2,%3};" \
        : "+f"((c)[0]), "+f"((c)[1]), "+f"((c)[2]), "+f"((c)[3]) \
        : "r"((a)[0]), "r"((a)[1]), "r"((a)[2]), "r"((a)[3]), "r"(b0), "r"(b1))

// swizzled smem address: 128B rows, 16B chunk index XOR (row&7)
__device__ __forceinline__ uint32_t swadr(uint32_t base, int row, int bytecol) {
    return base + row*128 + ((((bytecol >> 4) ^ (row & 7)) << 4));
}
__device__ __forceinline__ void packhl(float a, float b, uint32_t& h, uint32_t& l) {
    __nv_bfloat16 ah = __float2bfloat16(a), bh = __float2bfloat16(b);
    float ra = a - __bfloat162float(ah), rb = b - __bfloat162float(bh);
    __nv_bfloat16 al = __float2bfloat16(ra), bl = __float2bfloat16(rb);
    h = (uint32_t)__bfloat16_as_ushort(ah) | ((uint32_t)__bfloat16_as_ushort(bh) << 16);
    l = (uint32_t)__bfloat16_as_ushort(al) | ((uint32_t)__bfloat16_as_ushort(bl) << 16);
}
__device__ __forceinline__ uint32_t pack2(float a, float b) {
    __nv_bfloat162 p = __floats2bfloat162_rn(a, b);    // x=a (low), y=b (high)
    return *reinterpret_cast<uint32_t*>(&p);
}

// smem: Qh 0..8K, Ql 8K..16K ; buf b at 16384 + b*16384 : [Kh 8K | Vh 8K]
#define SBUF(b)    (16384 + (b)*16384)
#define SMEM_FLASH 49152

// ---------------- Kernel 1: QKV projection + quantum map + packing ----------------
// 256 thr, 128 rows/block; thread: rows rg,rg+32,rg+64,rg+96 x cols c0..c0+7.
__global__ void __launch_bounds__(256) qkv_kernel(
    const float* __restrict__ x,
    const float* __restrict__ wq, const float* __restrict__ bq,
    const float* __restrict__ wk, const float* __restrict__ bk,
    const float* __restrict__ wv, const float* __restrict__ bv,
    const float* __restrict__ theta)
{
    extern __shared__ float sm1[];
    float* wt = sm1;            // [64][65]
    float* xs = sm1 + 4160;     // [128][65]
    float* bs = sm1 + 12480;    // [64]
    float* cs = bs + 64;        // [64]

    const int tid  = threadIdx.x;
    const int m    = blockIdx.y;
    const int row0 = blockIdx.x * 128;

    const float* w  = (m == 0) ? wq : ((m == 1) ? wk : wv);
    const float* bb = (m == 0) ? bq : ((m == 1) ? bk : bv);
    for (int i = tid; i < 4096; i += 256)
        wt[(i >> 6)*65 + (i & 63)] = w[i];
    if (tid < 64) {
        bs[tid] = bb[tid];
        cs[tid] = ((m == 0) ? SCALE : 1.0f) * __cosf(theta[tid]);
    }
    for (int i = tid; i < 8192; i += 256)
        xs[(i >> 6)*65 + (i & 63)] = x[(size_t)row0*64 + i];
    __syncthreads();

    const int rg = tid & 31;
    const int c0 = (tid >> 5) * 8;

    float acc[4][8];
    #pragma unroll
    for (int i = 0; i < 4; i++)
        #pragma unroll
        for (int j = 0; j < 8; j++) acc[i][j] = bs[c0 + j];

    #pragma unroll 8
    for (int d = 0; d < 64; d++) {
        float wv8[8];
        #pragma unroll
        for (int j = 0; j < 8; j++) wv8[j] = wt[(c0 + j)*65 + d];
        #pragma unroll
        for (int i = 0; i < 4; i++) {
            float xv = xs[(rg + 32*i)*65 + d];
            #pragma unroll
            for (int j = 0; j < 8; j++)
                acc[i][j] = fmaf(xv, wv8[j], acc[i][j]);
        }
    }

    #pragma unroll
    for (int i = 0; i < 4; i++) {
        const int gr = row0 + rg + 32*i;
        float v[8];
        #pragma unroll
        for (int j = 0; j < 8; j++)
            v[j] = cs[c0 + j] * __cosf(acc[i][j]);

        const int wd0 = ((((c0 >> 3) ^ (gr & 7)) << 2));
        if (m == 0) {
            #pragma unroll
            for (int p = 0; p < 4; p++) {
                uint32_t hw, lw;
                packhl(v[2*p], v[2*p + 1], hw, lw);
                g_qh[gr*32 + wd0 + p] = hw;
                g_ql[gr*32 + wd0 + p] = lw;
            }
        } else {
            uint32_t* dst = (m == 1) ? g_kh : g_vh;
            #pragma unroll
            for (int p = 0; p < 4; p++)
                dst[gr*32 + wd0 + p] = pack2(v[2*p], v[2*p + 1]);
        }
    }
}

// ---------------- tile copy: 64 keys x (Kh, Vh), pre-swizzled ----------------
__device__ __forceinline__ void copy_tile(uint32_t sb, int tid, int buf, int kb) {
    #pragma unroll
    for (int j = 0; j < 4; j++) {
        int c = j*256 + tid;        // 0..1023
        int arr = c >> 9;           // 0:kh 1:vh (constant per j)
        int rem = c & 511;
        int row = rem >> 3, ch = rem & 7;
        const uint32_t* sp = arr ? g_vh : g_kh;
        cp16(sb + SBUF(buf) + arr*8192 + row*128 + ch*16,
             sp + (size_t)(kb*64 + row)*32 + ch*4);
    }
}

// ---------------- Kernel 2: bf16 flash attention, 8 warps, key-split ----------------
__global__ void __launch_bounds__(256, 1) flash_kernel()
{
    extern __shared__ char smem[];
    uint32_t sb = smem_u32(smem);
    const int tid  = threadIdx.x;
    const int wid  = tid >> 5;
    const int lane = tid & 31;
    const int qb   = blockIdx.x;            // 64 q-rows per CTA
    const int kg   = wid >> 2;              // key group: 0 -> keys 0-31, 1 -> keys 32-63
    const int wq4  = wid & 3;               // q-row quarter: rows wq4*16..+15

    // ---- prologue copies: Qh, Ql, tile0, tile1 ----
    #pragma unroll
    for (int j = 0; j < 4; j++) {
        int c = j*256 + tid;
        int arr = c >> 9;                   // 0:qh 1:ql
        int rem = c & 511;
        int row = rem >> 3, ch = rem & 7;
        const uint32_t* sp = arr ? g_ql : g_qh;
        cp16(sb + arr*8192 + row*128 + ch*16,
             sp + (size_t)(qb*64 + row)*32 + ch*4);
    }
    CP_COMMIT();
    copy_tile(sb, tid, 0, 0); CP_COMMIT();
    copy_tile(sb, tid, 1, 1); CP_COMMIT();
    CP_WAIT(2);
    __syncthreads();

    // ---- Q A-fragments (persistent) ----
    uint32_t qh[4][4], ql[4][4];
    {
        const int row = wq4*16 + (lane & 15);
        const int cb  = (lane >> 4) * 16;
        #pragma unroll
        for (int kc = 0; kc < 4; kc++) {
            LDSM4(qh[kc], swadr(sb,        row, 32*kc + cb));
            LDSM4(ql[kc], swadr(sb + 8192, row, 32*kc + cb));
        }
    }

    float o[8][4];
    #pragma unroll
    for (int db = 0; db < 8; db++)
        #pragma unroll
        for (int i = 0; i < 4; i++) o[db][i] = 0.f;
    float lg = 0.f, lg8 = 0.f;

    const int li = lane & 7, ls = lane >> 3;
    const int lr = (lane >> 3) & 1, lc = lane >> 4;
    const int nb0 = kg * 4;

    #pragma unroll 1
    for (int kb = 0; kb < 128; kb++) {
        const int b = kb & 1;
        if (kb < 126) { CP_WAIT(1); } else { CP_WAIT(0); }
        __syncthreads();

        const uint32_t kbh = sb + SBUF(b);
        const uint32_t vbh = kbh + 8192;

        // ---- S = q . kh  (2-term: (qh + ql) x kh) over this group's 32 keys ----
        float sc[4][4];
        #pragma unroll
        for (int ln = 0; ln < 4; ln++)
            #pragma unroll
            for (int t = 0; t < 4; t++) sc[ln][t] = 0.f;

        #pragma unroll
        for (int ln = 0; ln < 4; ln++) {
            const int nb = nb0 + ln;
            #pragma unroll
            for (int kcp = 0; kcp < 2; kcp++) {
                uint32_t kf[4];
                LDSM4(kf, swadr(kbh, nb*8 + li, 64*kcp + ls*16));
                MMA(sc[ln], qh[kcp*2 + 0], kf[0], kf[1]);
                MMA(sc[ln], ql[kcp*2 + 0], kf[0], kf[1]);
                MMA(sc[ln], qh[kcp*2 + 1], kf[2], kf[3]);
                MMA(sc[ln], ql[kcp*2 + 1], kf[2], kf[3]);
            }
        }

        // ---- exp (no max; bounded scores) + pack P ----
        uint32_t ph[2][4];
        #pragma unroll
        for (int ln = 0; ln < 4; ln++) {
            float e0 = __expf(sc[ln][0]), e1 = __expf(sc[ln][1]);
            float e2 = __expf(sc[ln][2]), e3 = __expf(sc[ln][3]);
            lg  += e0 + e1;
            lg8 += e2 + e3;
            const int kcl = ln >> 1, rb = (ln & 1) * 2;
            ph[kcl][rb + 0] = pack2(e0, e1);
            ph[kcl][rb + 1] = pack2(e2, e3);
        }

        // ---- O += P V (single-term bf16) over this group's 32 keys ----
        #pragma unroll
        for (int kcl = 0; kcl < 2; kcl++) {
            const int kcg = kg*2 + kcl;
            uint32_t vf[4][4];
            #pragma unroll
            for (int dp = 0; dp < 4; dp++)
                LDSM4T(vf[dp], swadr(vbh, kcg*16 + lr*8 + li, 32*dp + lc*16));
            #pragma unroll
            for (int db = 0; db < 8; db++)
                MMA(o[db], ph[kcl], vf[db>>1][(db&1)*2], vf[db>>1][(db&1)*2+1]);
        }

        __syncthreads();
        if (kb + 2 < 128) { copy_tile(sb, tid, b, kb + 2); CP_COMMIT(); }
    }

    // ---- reduce l within quad ----
    lg  += __shfl_xor_sync(0xffffffffu, lg, 1);
    lg  += __shfl_xor_sync(0xffffffffu, lg, 2);
    lg8 += __shfl_xor_sync(0xffffffffu, lg8, 1);
    lg8 += __shfl_xor_sync(0xffffffffu, lg8, 2);

    // ---- cross-keygroup reduction via smem (buffers are free now) ----
    float* red  = (float*)(smem + 16384);            // [4][32][32]
    float* redl = (float*)(smem + 16384 + 16384);    // [4][32][2]
    __syncthreads();
    if (kg == 1) {
        float* dst = red + (wq4*32 + lane)*32;
        #pragma unroll
        for (int db = 0; db < 8; db++)
            #pragma unroll
            for (int t = 0; t < 4; t++) dst[db*4 + t] = o[db][t];
        redl[(wq4*32 + lane)*2 + 0] = lg;
        redl[(wq4*32 + lane)*2 + 1] = lg8;
    }
    __syncthreads();
    if (kg == 0) {
        const float* src = red + (wq4*32 + lane)*32;
        #pragma unroll
        for (int db = 0; db < 8; db++)
            #pragma unroll
            for (int t = 0; t < 4; t++) o[db][t] += src[db*4 + t];
        lg  += redl[(wq4*32 + lane)*2 + 0];
        lg8 += redl[(wq4*32 + lane)*2 + 1];

        const float ig = 1.f/lg, ig8 = 1.f/lg8;
        const int gq = lane >> 2, t = lane & 3;
        const int n = qb*64 + wq4*16 + gq;
        #pragma unroll
        for (int db = 0; db < 8; db++) {
            int d = db*8 + 2*t;
            *reinterpret_cast<float2*>(&g_ov[(size_t)n*64 + d])       = make_float2(o[db][0]*ig,  o[db][1]*ig);
            *reinterpret_cast<float2*>(&g_ov[(size_t)(n + 8)*64 + d]) = make_float2(o[db][2]*ig8, o[db][3]*ig8);
        }
    }
}

// ---------------- Kernel 3: output projection ----------------
__global__ void __launch_bounds__(256) proj_kernel(
    const float* __restrict__ wo, const float* __restrict__ bo,
    float* __restrict__ out)
{
    __shared__ float wt[64*65];
    __shared__ float bs[64];
    __shared__ float os[32*64];
    const int tid = threadIdx.x;
    const int row0 = blockIdx.x * 32;
    for (int i = tid; i < 4096; i += 256)
        wt[(i >> 6)*65 + (i & 63)] = wo[i];
    if (tid < 64) bs[tid] = bo[tid];
    for (int i = tid; i < 2048; i += 256)
        os[i] = g_ov[(size_t)row0*64 + i];
    __syncthreads();

    for (int tI = tid; tI < 2048; tI += 256) {
        int row = tI >> 6, col = tI & 63;
        float acc = bs[col];
        const float* wrow = &wt[col*65];
        const float* orow = &os[row*64];
        #pragma unroll
        for (int d = 0; d < 64; d++)
            acc = fmaf(orow[d], wrow[d], acc);
        out[(row0 + row)*64 + col] = acc;
    }
}

// ---------------- launch ----------------
extern "C" void kernel_launch(void* const* d_in, const int* in_sizes, int n_in,
                              void* d_out, int out_size)
{
    const float* x  = (const float*)d_in[0];
    const float* wq = (const float*)d_in[1];
    const float* bq = (const float*)d_in[2];
    const float* wk = (const float*)d_in[3];
    const float* bk = (const float*)d_in[4];
    const float* wv = (const float*)d_in[5];
    const float* bv = (const float*)d_in[6];
    const float* th = (const float*)d_in[7];
    const float* wo = (const float*)d_in[8];
    const float* bo = (const float*)d_in[9];
    float* out = (float*)d_out;

    const int QKV_SMEM = 12608 * 4;   // 50432 B
    cudaFuncSetAttribute(qkv_kernel,  cudaFuncAttributeMaxDynamicSharedMemorySize, QKV_SMEM);
    cudaFuncSetAttribute(flash_kernel, cudaFuncAttributeMaxDynamicSharedMemorySize, SMEM_FLASH);

    qkv_kernel<<<dim3(NTOK/128, 3), 256, QKV_SMEM>>>(x, wq, bq, wk, bk, wv, bv, th);
    flash_kernel<<<128, 256, SMEM_FLASH>>>();
    proj_kernel<<<NTOK/32, 256>>>(wo, bo, out);
}

// round 7
// speedup vs baseline: 4.7227x; 1.3478x over previous
#include <cuda_runtime.h>
#include <cuda_bf16.h>
#include <cstdint>

#define NTOK 8192
#define EDIM 64
#define SCALE 0.35355339059327373f   // 1/sqrt(8)

// packed bf16x2 words: [row][32 words], SW128-swizzled 16B chunks within 128B rows.
__device__ uint32_t g_qh[NTOK*32];
__device__ uint32_t g_kh[NTOK*32];
__device__ uint32_t g_vh[NTOK*32];
__device__ float    g_opart[2][NTOK][EDIM];   // unnormalized O per KV-half
__device__ float    g_lpart[2][NTOK];         // softmax denominator per KV-half

// ======================= helpers =======================
__device__ __forceinline__ uint32_t smem_u32(const void* p) {
    uint32_t a;
    asm("{ .reg .u64 t; cvta.to.shared.u64 t, %1; cvt.u32.u64 %0, t; }" : "=r"(a) : "l"(p));
    return a;
}
__device__ __forceinline__ void cp16(uint32_t dst, const void* src) {
    asm volatile("{ .reg .u64 g; cvta.to.global.u64 g, %1; cp.async.cg.shared.global [%0], [g], 16; }"
                 :: "r"(dst), "l"(src) : "memory");
}
#define CP_COMMIT() asm volatile("cp.async.commit_group;" ::: "memory")
#define CP_WAIT(n)  asm volatile("cp.async.wait_group %0;" :: "n"(n) : "memory")

#define LDSM4(r, a) \
    asm volatile("ldmatrix.sync.aligned.m8n8.x4.shared.b16 {%0,%1,%2,%3}, [%4];" \
        : "=r"((r)[0]), "=r"((r)[1]), "=r"((r)[2]), "=r"((r)[3]) : "r"(a))
#define LDSM4T(r, a) \
    asm volatile("ldmatrix.sync.aligned.m8n8.x4.trans.shared.b16 {%0,%1,%2,%3}, [%4];" \
        : "=r"((r)[0]), "=r"((r)[1]), "=r"((r)[2]), "=r"((r)[3]) : "r"(a))

#define MMA(c, a, b0, b1) \
    asm volatile("mma.sync.aligned.m16n8k16.row.col.f32.bf16.bf16.f32 " \
        "{%0,%1,%2,%3}, {%4,%5,%6,%7}, {%8,%9}, {%0,%1,%2,%3};" \
        : "+f"((c)[0]), "+f"((c)[1]), "+f"((c)[2]), "+f"((c)[3]) \
        : "r"((a)[0]), "r"((a)[1]), "r"((a)[2]), "r"((a)[3]), "r"(b0), "r"(b1))

// swizzled smem address: 128B rows, 16B chunk index XOR (row&7)
__device__ __forceinline__ uint32_t swadr(uint32_t base, int row, int bytecol) {
    return base + row*128 + ((((bytecol >> 4) ^ (row & 7)) << 4));
}
__device__ __forceinline__ uint32_t pack2(float a, float b) {
    __nv_bfloat162 p = __floats2bfloat162_rn(a, b);    // x=a (low), y=b (high)
    return *reinterpret_cast<uint32_t*>(&p);
}

// smem: Qh 0..8K ; buf b at 8192 + b*16384 : [Kh 8K | Vh 8K]
#define SBUF(b)    (8192 + (b)*16384)
#define SMEM_FLASH 40960

// ---------------- Kernel 1: QKV projection + quantum map + bf16 packing ----------------
// 256 thr, 64 rows/block; thread: rows rg, rg+32 x cols c0..c0+7.
__global__ void __launch_bounds__(256) qkv_kernel(
    const float* __restrict__ x,
    const float* __restrict__ wq, const float* __restrict__ bq,
    const float* __restrict__ wk, const float* __restrict__ bk,
    const float* __restrict__ wv, const float* __restrict__ bv,
    const float* __restrict__ theta)
{
    __shared__ float wtT[64*64];   // [d][col] (transposed for float4 broadcast loads)
    __shared__ float xs[64*65];    // [row][d] padded
    __shared__ float bs[64];
    __shared__ float cs[64];

    const int tid  = threadIdx.x;
    const int m    = blockIdx.y;
    const int row0 = blockIdx.x * 64;

    const float* w  = (m == 0) ? wq : ((m == 1) ? wk : wv);
    const float* bb = (m == 0) ? bq : ((m == 1) ? bk : bv);
    for (int i = tid; i < 4096; i += 256) {
        int col = i >> 6, d = i & 63;
        wtT[d*64 + col] = w[i];
    }
    if (tid < 64) {
        bs[tid] = bb[tid];
        cs[tid] = ((m == 0) ? SCALE : 1.0f) * __cosf(theta[tid]);
    }
    for (int i = tid; i < 4096; i += 256)
        xs[(i >> 6)*65 + (i & 63)] = x[(size_t)row0*64 + i];
    __syncthreads();

    const int rg = tid & 31;
    const int c0 = (tid >> 5) * 8;

    float acc[2][8];
    #pragma unroll
    for (int i = 0; i < 2; i++)
        #pragma unroll
        for (int j = 0; j < 8; j++) acc[i][j] = bs[c0 + j];

    #pragma unroll 8
    for (int d = 0; d < 64; d++) {
        float4 w0 = *reinterpret_cast<float4*>(&wtT[d*64 + c0]);
        float4 w1 = *reinterpret_cast<float4*>(&wtT[d*64 + c0 + 4]);
        float wv8[8] = {w0.x, w0.y, w0.z, w0.w, w1.x, w1.y, w1.z, w1.w};
        float xv0 = xs[rg*65 + d];
        float xv1 = xs[(rg + 32)*65 + d];
        #pragma unroll
        for (int j = 0; j < 8; j++) {
            acc[0][j] = fmaf(xv0, wv8[j], acc[0][j]);
            acc[1][j] = fmaf(xv1, wv8[j], acc[1][j]);
        }
    }

    uint32_t* dst = (m == 0) ? g_qh : ((m == 1) ? g_kh : g_vh);
    #pragma unroll
    for (int i = 0; i < 2; i++) {
        const int gr = row0 + rg + 32*i;
        float v[8];
        #pragma unroll
        for (int j = 0; j < 8; j++)
            v[j] = cs[c0 + j] * __cosf(acc[i][j]);
        const int wd0 = ((((c0 >> 3) ^ (gr & 7)) << 2));
        #pragma unroll
        for (int p = 0; p < 4; p++)
            dst[gr*32 + wd0 + p] = pack2(v[2*p], v[2*p + 1]);
    }
}

// ---------------- tile copy: 64 keys x (Kh, Vh), pre-swizzled ----------------
__device__ __forceinline__ void copy_tile(uint32_t sb, int tid, int buf, int kt) {
    #pragma unroll
    for (int j = 0; j < 4; j++) {
        int c = j*256 + tid;        // 0..1023
        int arr = c >> 9;           // 0:kh 1:vh (constant per j)
        int rem = c & 511;
        int row = rem >> 3, ch = rem & 7;
        const uint32_t* sp = arr ? g_vh : g_kh;
        cp16(sb + SBUF(buf) + arr*8192 + row*128 + ch*16,
             sp + (size_t)(kt*64 + row)*32 + ch*4);
    }
}

// ---------------- Kernel 2: bf16 flash attention, split-KV x2, 8 warps key-split ----
__global__ void __launch_bounds__(256, 2) flash_kernel()
{
    extern __shared__ char smem[];
    uint32_t sb = smem_u32(smem);
    const int tid  = threadIdx.x;
    const int wid  = tid >> 5;
    const int lane = tid & 31;
    const int qb   = blockIdx.x >> 1;       // 64 q-rows per CTA
    const int half = blockIdx.x & 1;        // KV half: tiles half*64 .. +63
    const int kt0  = half * 64;
    const int kg   = wid >> 2;              // key group: 0 -> keys 0-31, 1 -> keys 32-63
    const int wq4  = wid & 3;               // q-row quarter: rows wq4*16..+15

    // ---- prologue copies: Qh, tile0, tile1 ----
    #pragma unroll
    for (int j = 0; j < 2; j++) {
        int c = j*256 + tid;
        int row = c >> 3, ch = c & 7;
        cp16(sb + row*128 + ch*16, g_qh + (size_t)(qb*64 + row)*32 + ch*4);
    }
    CP_COMMIT();
    copy_tile(sb, tid, 0, kt0 + 0); CP_COMMIT();
    copy_tile(sb, tid, 1, kt0 + 1); CP_COMMIT();
    CP_WAIT(2);
    __syncthreads();

    // ---- Q A-fragments (persistent, single bf16 term) ----
    uint32_t qh[4][4];
    {
        const int row = wq4*16 + (lane & 15);
        const int cb  = (lane >> 4) * 16;
        #pragma unroll
        for (int kc = 0; kc < 4; kc++)
            LDSM4(qh[kc], swadr(sb, row, 32*kc + cb));
    }

    float o[8][4];
    #pragma unroll
    for (int db = 0; db < 8; db++)
        #pragma unroll
        for (int i = 0; i < 4; i++) o[db][i] = 0.f;
    float lg = 0.f, lg8 = 0.f;

    const int li = lane & 7, ls = lane >> 3;
    const int lr = (lane >> 3) & 1, lc = lane >> 4;
    const int nb0 = kg * 4;

    #pragma unroll 1
    for (int kb = 0; kb < 64; kb++) {
        const int b = kb & 1;
        if (kb < 62) { CP_WAIT(1); } else { CP_WAIT(0); }
        __syncthreads();

        const uint32_t kbh = sb + SBUF(b);
        const uint32_t vbh = kbh + 8192;

        // ---- S = qh . kh (single-term bf16) over this group's 32 keys ----
        float sc[4][4];
        #pragma unroll
        for (int ln = 0; ln < 4; ln++)
            #pragma unroll
            for (int t = 0; t < 4; t++) sc[ln][t] = 0.f;

        #pragma unroll
        for (int ln = 0; ln < 4; ln++) {
            const int nb = nb0 + ln;
            #pragma unroll
            for (int kcp = 0; kcp < 2; kcp++) {
                uint32_t kf[4];
                LDSM4(kf, swadr(kbh, nb*8 + li, 64*kcp + ls*16));
                MMA(sc[ln], qh[kcp*2 + 0], kf[0], kf[1]);
                MMA(sc[ln], qh[kcp*2 + 1], kf[2], kf[3]);
            }
        }

        // ---- exp (no max; bounded scores) + pack P ----
        uint32_t ph[2][4];
        #pragma unroll
        for (int ln = 0; ln < 4; ln++) {
            float e0 = __expf(sc[ln][0]), e1 = __expf(sc[ln][1]);
            float e2 = __expf(sc[ln][2]), e3 = __expf(sc[ln][3]);
            lg  += e0 + e1;
            lg8 += e2 + e3;
            const int kcl = ln >> 1, rb = (ln & 1) * 2;
            ph[kcl][rb + 0] = pack2(e0, e1);
            ph[kcl][rb + 1] = pack2(e2, e3);
        }

        // ---- O += P V (single-term bf16) over this group's 32 keys ----
        #pragma unroll
        for (int kcl = 0; kcl < 2; kcl++) {
            const int kcg = kg*2 + kcl;
            uint32_t vf[4][4];
            #pragma unroll
            for (int dp = 0; dp < 4; dp++)
                LDSM4T(vf[dp], swadr(vbh, kcg*16 + lr*8 + li, 32*dp + lc*16));
            #pragma unroll
            for (int db = 0; db < 8; db++)
                MMA(o[db], ph[kcl], vf[db>>1][(db&1)*2], vf[db>>1][(db&1)*2+1]);
        }

        __syncthreads();
        if (kb + 2 < 64) { copy_tile(sb, tid, b, kt0 + kb + 2); CP_COMMIT(); }
    }

    // ---- reduce l within quad ----
    lg  += __shfl_xor_sync(0xffffffffu, lg, 1);
    lg  += __shfl_xor_sync(0xffffffffu, lg, 2);
    lg8 += __shfl_xor_sync(0xffffffffu, lg8, 1);
    lg8 += __shfl_xor_sync(0xffffffffu, lg8, 2);

    // ---- cross-keygroup reduction via smem (buffers are free now) ----
    float* red  = (float*)(smem + 8192);             // [4][32][32]
    float* redl = (float*)(smem + 8192 + 16384);     // [4][32][2]
    __syncthreads();
    if (kg == 1) {
        float* dst = red + (wq4*32 + lane)*32;
        #pragma unroll
        for (int db = 0; db < 8; db++)
            #pragma unroll
            for (int t = 0; t < 4; t++) dst[db*4 + t] = o[db][t];
        redl[(wq4*32 + lane)*2 + 0] = lg;
        redl[(wq4*32 + lane)*2 + 1] = lg8;
    }
    __syncthreads();
    if (kg == 0) {
        const float* src = red + (wq4*32 + lane)*32;
        #pragma unroll
        for (int db = 0; db < 8; db++)
            #pragma unroll
            for (int t = 0; t < 4; t++) o[db][t] += src[db*4 + t];
        lg  += redl[(wq4*32 + lane)*2 + 0];
        lg8 += redl[(wq4*32 + lane)*2 + 1];

        const int gq = lane >> 2, t = lane & 3;
        const int n = qb*64 + wq4*16 + gq;
        #pragma unroll
        for (int db = 0; db < 8; db++) {
            int d = db*8 + 2*t;
            *reinterpret_cast<float2*>(&g_opart[half][n][d])     = make_float2(o[db][0], o[db][1]);
            *reinterpret_cast<float2*>(&g_opart[half][n + 8][d]) = make_float2(o[db][2], o[db][3]);
        }
        if (t == 0) {
            g_lpart[half][n]     = lg;
            g_lpart[half][n + 8] = lg8;
        }
    }
}

// ---------------- Kernel 3: combine halves + output projection ----------------
__global__ void __launch_bounds__(256) proj_kernel(
    const float* __restrict__ wo, const float* __restrict__ bo,
    float* __restrict__ out)
{
    __shared__ float wt[64*65];
    __shared__ float bs[64];
    __shared__ float os[32*64];
    __shared__ float linv[32];
    const int tid = threadIdx.x;
    const int row0 = blockIdx.x * 32;
    for (int i = tid; i < 4096; i += 256)
        wt[(i >> 6)*65 + (i & 63)] = wo[i];
    if (tid < 64) bs[tid] = bo[tid];
    if (tid < 32) {
        int n = row0 + tid;
        linv[tid] = 1.0f / (g_lpart[0][n] + g_lpart[1][n]);
    }
    __syncthreads();
    for (int i = tid; i < 2048; i += 256) {
        int row = i >> 6, d = i & 63;
        int n = row0 + row;
        os[i] = (g_opart[0][n][d] + g_opart[1][n][d]) * linv[row];
    }
    __syncthreads();

    for (int tI = tid; tI < 2048; tI += 256) {
        int row = tI >> 6, col = tI & 63;
        float acc = bs[col];
        const float* wrow = &wt[col*65];
        const float* orow = &os[row*64];
        #pragma unroll
        for (int d = 0; d < 64; d++)
            acc = fmaf(orow[d], wrow[d], acc);
        out[(row0 + row)*64 + col] = acc;
    }
}

// ---------------- launch ----------------
extern "C" void kernel_launch(void* const* d_in, const int* in_sizes, int n_in,
                              void* d_out, int out_size)
{
    const float* x  = (const float*)d_in[0];
    const float* wq = (const float*)d_in[1];
    const float* bq = (const float*)d_in[2];
    const float* wk = (const float*)d_in[3];
    const float* bk = (const float*)d_in[4];
    const float* wv = (const float*)d_in[5];
    const float* bv = (const float*)d_in[6];
    const float* th = (const float*)d_in[7];
    const float* wo = (const float*)d_in[8];
    const float* bo = (const float*)d_in[9];
    float* out = (float*)d_out;

    cudaFuncSetAttribute(flash_kernel, cudaFuncAttributeMaxDynamicSharedMemorySize, SMEM_FLASH);

    qkv_kernel<<<dim3(NTOK/64, 3), 256>>>(x, wq, bq, wk, bk, wv, bv, th);
    flash_kernel<<<256, 256, SMEM_FLASH>>>();
    proj_kernel<<<NTOK/32, 256>>>(wo, bo, out);
}